// round 10
// baseline (speedup 1.0000x reference)
#include <cuda_runtime.h>

#define BB 2
#define CC 512
#define HH 256
#define WW 256
#define EPSV 1e-5f
#define NCTA 148            // persistent-kernel grid for kmid

// ---------------- scratch (device globals; no allocations allowed) ----------
__device__ float g_y1[BB * CC * WW];     // [b][c][w]
__device__ float g_y2[BB * CC * HH];     // [b][c][h]
__device__ float g_dot[CC * BB];         // flat [c][b]; linear view == num[b][k]
__device__ float g_h[BB * 2 * CC];       // [b][1024]
__device__ float g_logits[BB * CC];      // [b][c]
__device__ float g_scale[BB * CC];       // [b][c]

__device__ unsigned g_cnt[3];            // grid-barrier arrival counters
__device__ unsigned g_gen[3];            // grid-barrier generations (monotone)

__device__ __forceinline__ float4 ldcg4(const float4* p) { return __ldcg(p); }
__device__ __forceinline__ void prefetchL2(const void* p) {
    asm volatile("prefetch.global.L2 [%0];" :: "l"(p));
}
__device__ __forceinline__ float hsum4(float4 a) { return (a.x + a.y) + (a.z + a.w); }
__device__ __forceinline__ float dotp4(float4 a, float4 b) {
    return a.x * b.x + a.y * b.y + a.z * b.z + a.w * b.w;
}
__device__ __forceinline__ float4 relu4(float4 a, float r, float c) {
    float4 o;
    o.x = fmaxf(0.f, fmaf(a.x, r, c));
    o.y = fmaxf(0.f, fmaf(a.y, r, c));
    o.z = fmaxf(0.f, fmaf(a.z, r, c));
    o.w = fmaxf(0.f, fmaf(a.w, r, c));
    return o;
}

// ============================================================================
// k1: per-(b,c) plane: y1[w] = sum_h x[h][w]*w1[h], y2[h] = sum_w x[h][w]*w2[w]
// grid = B*C = 1024, block = 256 (8 warps).
// Warp wrp owns rows {wrp + 8k, k=0..31}; each lane covers 8 columns of the
// row (2 float4). The cross-lane y2 reduction is DEFERRED: the hot loop only
// stores the per-lane partial dot to smem (1 conflict-free STS per row), so
// the load stream has no shuffle chain / predication in its way.
// ============================================================================
__global__ __launch_bounds__(256) void k1(const float* __restrict__ x,
                                          const float* __restrict__ w1,
                                          const float* __restrict__ w2) {
    int bc = blockIdx.x;                 // b*CC + c
    int c  = bc & (CC - 1);
    const float4* plane = reinterpret_cast<const float4*>(x) + (size_t)bc * (HH * WW / 4);

    __shared__ float  w1s[HH];
    __shared__ float  w2s[WW];
    __shared__ float4 y1p[8][64];        // per-warp y1 partials (8 KB)
    __shared__ float  pbuf[HH][33];      // per-(row,lane) dot partials, padded

    int t    = threadIdx.x;
    int lane = t & 31;
    int wrp  = t >> 5;

    w1s[t] = w1[c * HH + t];
    w2s[t] = w2[c * WW + t];
    __syncthreads();

    float4 w2a = reinterpret_cast<const float4*>(w2s)[lane];
    float4 w2b = reinterpret_cast<const float4*>(w2s)[lane + 32];
    float4 acc1a = make_float4(0.f, 0.f, 0.f, 0.f);
    float4 acc1b = make_float4(0.f, 0.f, 0.f, 0.f);

    #pragma unroll 4
    for (int k = 0; k < 32; ++k) {
        int row = wrp + 8 * k;
        float4 v0 = plane[row * 64 + lane];
        float4 v1 = plane[row * 64 + lane + 32];
        float  wv = w1s[row];
        acc1a.x = fmaf(v0.x, wv, acc1a.x);
        acc1a.y = fmaf(v0.y, wv, acc1a.y);
        acc1a.z = fmaf(v0.z, wv, acc1a.z);
        acc1a.w = fmaf(v0.w, wv, acc1a.w);
        acc1b.x = fmaf(v1.x, wv, acc1b.x);
        acc1b.y = fmaf(v1.y, wv, acc1b.y);
        acc1b.z = fmaf(v1.z, wv, acc1b.z);
        acc1b.w = fmaf(v1.w, wv, acc1b.w);
        pbuf[row][lane] = dotp4(v0, w2a) + dotp4(v1, w2b);
    }

    y1p[wrp][lane]      = acc1a;
    y1p[wrp][lane + 32] = acc1b;
    __syncthreads();

    // y2[t] = sum over 32 lane-partials of row t (stride-33 => conflict-free)
    {
        float s0 = 0.f, s1 = 0.f, s2 = 0.f, s3 = 0.f;
        #pragma unroll
        for (int i = 0; i < 8; ++i) {
            s0 += pbuf[t][4 * i + 0];
            s1 += pbuf[t][4 * i + 1];
            s2 += pbuf[t][4 * i + 2];
            s3 += pbuf[t][4 * i + 3];
        }
        g_y2[bc * HH + t] = (s0 + s1) + (s2 + s3);
    }

    if (t < 64) {
        float4 s = y1p[0][t];
        #pragma unroll
        for (int i = 1; i < 8; ++i) {
            float4 a = y1p[i][t];
            s.x += a.x; s.y += a.y; s.z += a.z; s.w += a.w;
        }
        reinterpret_cast<float4*>(g_y1 + (size_t)bc * WW)[t] = s;
    }
}

// ============================================================================
// software grid barrier: all NCTA CTAs co-resident (NCTA <= #SMs).
// ============================================================================
__device__ __forceinline__ void gridbar(int i) {
    __syncthreads();
    if (threadIdx.x == 0) {
        __threadfence();
        volatile unsigned* genp = (volatile unsigned*)&g_gen[i];
        unsigned gen = *genp;                          // read BEFORE arriving
        unsigned arrived = atomicAdd(&g_cnt[i], 1u);
        if (arrived == NCTA - 1) {
            atomicExch(&g_cnt[i], 0u);                 // reset for next replay
            __threadfence();
            atomicAdd(&g_gen[i], 1u);                  // release
        } else {
            while (*genp == gen) { __nanosleep(32); }
        }
        __threadfence();
    }
    __syncthreads();
}

// ============================================================================
// kmid: fused BN+ReLU+dot -> linear1 -> linear2 -> softmax.
// Persistent, grid = NCTA, block = 256. MLP weights prefetched into L2.
// ============================================================================
__global__ __launch_bounds__(256) void kmid(const float* __restrict__ g1, const float* __restrict__ b1,
                                            const float* __restrict__ g2, const float* __restrict__ b2,
                                            const float* __restrict__ lw1, const float* __restrict__ lb1,
                                            const float* __restrict__ lw2, const float* __restrict__ lb2) {
    int t    = threadIdx.x;
    int lane = t & 31;
    int wrp  = t >> 5;
    int gw   = blockIdx.x * 8 + wrp;

    // ---- prefetch MLP weights into L2 (1 line per thread) ----
    {
        int gt = blockIdx.x * 256 + t;
        if (gt < 16384)          prefetchL2((const char*)lw1 + (size_t)gt * 128);
        else if (gt < 32768)     prefetchL2((const char*)lw2 + (size_t)(gt - 16384) * 128);
    }

    // ---- phase A: per-channel BN stats + ReLU + dot (one warp per channel) --
    if (gw < CC) {
        int c = gw;
        const float4* p10 = reinterpret_cast<const float4*>(g_y1 + c * WW);
        const float4* p11 = reinterpret_cast<const float4*>(g_y1 + CC * WW + c * WW);
        const float4* p20 = reinterpret_cast<const float4*>(g_y2 + c * HH);
        const float4* p21 = reinterpret_cast<const float4*>(g_y2 + CC * HH + c * HH);

        float4 a10a = ldcg4(p10 + lane), a10b = ldcg4(p10 + lane + 32);
        float4 a11a = ldcg4(p11 + lane), a11b = ldcg4(p11 + lane + 32);
        float4 a20a = ldcg4(p20 + lane), a20b = ldcg4(p20 + lane + 32);
        float4 a21a = ldcg4(p21 + lane), a21b = ldcg4(p21 + lane + 32);

        float s1 = hsum4(a10a) + hsum4(a10b) + hsum4(a11a) + hsum4(a11b);
        float q1 = dotp4(a10a, a10a) + dotp4(a10b, a10b) + dotp4(a11a, a11a) + dotp4(a11b, a11b);
        float s2 = hsum4(a20a) + hsum4(a20b) + hsum4(a21a) + hsum4(a21b);
        float q2 = dotp4(a20a, a20a) + dotp4(a20b, a20b) + dotp4(a21a, a21a) + dotp4(a21b, a21b);

        #pragma unroll
        for (int off = 16; off; off >>= 1) {
            s1 += __shfl_xor_sync(0xffffffffu, s1, off);
            q1 += __shfl_xor_sync(0xffffffffu, q1, off);
            s2 += __shfl_xor_sync(0xffffffffu, s2, off);
            q2 += __shfl_xor_sync(0xffffffffu, q2, off);
        }

        const float invn = 1.f / (float)(BB * WW);
        float m1 = s1 * invn, v1 = q1 * invn - m1 * m1;
        float m2 = s2 * invn, v2 = q2 * invn - m2 * m2;
        float r1 = rsqrtf(v1 + EPSV) * g1[c];
        float c1 = b1[c] - m1 * r1;
        float r2 = rsqrtf(v2 + EPSV) * g2[c];
        float c2 = b2[c] - m2 * r2;

        float d0 = dotp4(relu4(a10a, r1, c1), relu4(a20a, r2, c2))
                 + dotp4(relu4(a10b, r1, c1), relu4(a20b, r2, c2));
        float d1 = dotp4(relu4(a11a, r1, c1), relu4(a21a, r2, c2))
                 + dotp4(relu4(a11b, r1, c1), relu4(a21b, r2, c2));
        #pragma unroll
        for (int off = 16; off; off >>= 1) {
            d0 += __shfl_xor_sync(0xffffffffu, d0, off);
            d1 += __shfl_xor_sync(0xffffffffu, d1, off);
        }
        if (lane == 0) {
            g_dot[c * BB + 0] = d0;
            g_dot[c * BB + 1] = d1;
        }
    }

    gridbar(0);

    // ---- phase B: layer1, one warp per output row j (K=512) ----
    if (gw < 2 * CC) {
        int j = gw;
        const float4* wr = reinterpret_cast<const float4*>(lw1 + (size_t)j * CC);
        const float4* i0 = reinterpret_cast<const float4*>(g_dot);
        const float4* i1 = reinterpret_cast<const float4*>(g_dot + CC);
        float a0 = 0.f, a1 = 0.f;
        #pragma unroll
        for (int i = 0; i < 4; ++i) {
            float4 wq = __ldg(wr + lane + 32 * i);
            float4 v0 = ldcg4(i0 + lane + 32 * i);
            float4 v1 = ldcg4(i1 + lane + 32 * i);
            a0 += dotp4(wq, v0);
            a1 += dotp4(wq, v1);
        }
        #pragma unroll
        for (int off = 16; off; off >>= 1) {
            a0 += __shfl_xor_sync(0xffffffffu, a0, off);
            a1 += __shfl_xor_sync(0xffffffffu, a1, off);
        }
        if (lane == 0) {
            float bj = lb1[j];
            g_h[j]          = a0 + bj;
            g_h[2 * CC + j] = a1 + bj;
        }
    }

    gridbar(1);

    // ---- phase C: layer2, one warp per output row j (K=1024) ----
    if (gw < CC) {
        int j = gw;
        const float4* wr = reinterpret_cast<const float4*>(lw2 + (size_t)j * 2 * CC);
        const float4* i0 = reinterpret_cast<const float4*>(g_h);
        const float4* i1 = reinterpret_cast<const float4*>(g_h + 2 * CC);
        float a0 = 0.f, a1 = 0.f;
        #pragma unroll
        for (int i = 0; i < 8; ++i) {
            float4 wq = __ldg(wr + lane + 32 * i);
            float4 v0 = ldcg4(i0 + lane + 32 * i);
            float4 v1 = ldcg4(i1 + lane + 32 * i);
            a0 += dotp4(wq, v0);
            a1 += dotp4(wq, v1);
        }
        #pragma unroll
        for (int off = 16; off; off >>= 1) {
            a0 += __shfl_xor_sync(0xffffffffu, a0, off);
            a1 += __shfl_xor_sync(0xffffffffu, a1, off);
        }
        if (lane == 0) {
            float bj = lb2[j];
            g_logits[j]      = a0 + bj;
            g_logits[CC + j] = a1 + bj;
        }
    }

    gridbar(2);

    // ---- phase D: softmax over c per batch; CTA 0 only ----
    if (blockIdx.x == 0) {
        __shared__ float sh[8];
        #pragma unroll
        for (int b = 0; b < BB; ++b) {
            float v0 = __ldcg(&g_logits[b * CC + t]);
            float v1 = __ldcg(&g_logits[b * CC + 256 + t]);

            float m = fmaxf(v0, v1);
            #pragma unroll
            for (int off = 16; off; off >>= 1) m = fmaxf(m, __shfl_xor_sync(0xffffffffu, m, off));
            if (lane == 0) sh[wrp] = m;
            __syncthreads();
            if (t == 0) {
                float mm = sh[0];
                #pragma unroll
                for (int i = 1; i < 8; ++i) mm = fmaxf(mm, sh[i]);
                sh[0] = mm;
            }
            __syncthreads();
            m = sh[0];
            __syncthreads();

            float e0 = expf(v0 - m), e1 = expf(v1 - m);
            float s = e0 + e1;
            #pragma unroll
            for (int off = 16; off; off >>= 1) s += __shfl_xor_sync(0xffffffffu, s, off);
            if (lane == 0) sh[wrp] = s;
            __syncthreads();
            if (t == 0) {
                float ss = sh[0];
                #pragma unroll
                for (int i = 1; i < 8; ++i) ss += sh[i];
                sh[0] = ss;
            }
            __syncthreads();
            s = sh[0];
            __syncthreads();

            float inv = 1.f / s;
            g_scale[b * CC + t]       = e0 * inv;
            g_scale[b * CC + 256 + t] = e1 * inv;
        }
    }
}

// ============================================================================
// k4: out = x * scale[b,c]. Reversed plane order + streaming stores (the exact
// configuration of the 143.8us best).
// ============================================================================
__global__ __launch_bounds__(256) void k4(const float* __restrict__ x, float* __restrict__ out) {
    int idx  = (BB * CC * 8 - 1) - blockIdx.x;   // reversed schedule
    int bc   = idx >> 3;
    int part = idx & 7;
    float s = __ldcg(&g_scale[bc]);

    const float4* xp = reinterpret_cast<const float4*>(x)   + (size_t)bc * (HH * WW / 4) + part * 2048;
    float4*       op = reinterpret_cast<float4*>(out)       + (size_t)bc * (HH * WW / 4) + part * 2048;

    int t = threadIdx.x;
    #pragma unroll
    for (int i = 0; i < 8; ++i) {
        float4 v = xp[i * 256 + t];
        v.x *= s; v.y *= s; v.z *= s; v.w *= s;
        __stcs(&op[i * 256 + t], v);
    }
}

// ============================================================================
extern "C" void kernel_launch(void* const* d_in, const int* in_sizes, int n_in,
                              void* d_out, int out_size) {
    const float* x   = (const float*)d_in[0];
    const float* w1  = (const float*)d_in[1];
    const float* w2  = (const float*)d_in[2];
    const float* g1  = (const float*)d_in[3];
    const float* b1  = (const float*)d_in[4];
    const float* g2  = (const float*)d_in[5];
    const float* b2  = (const float*)d_in[6];
    const float* lw1 = (const float*)d_in[7];
    const float* lb1 = (const float*)d_in[8];
    const float* lw2 = (const float*)d_in[9];
    const float* lb2 = (const float*)d_in[10];
    float* out = (float*)d_out;

    k1<<<BB * CC, 256>>>(x, w1, w2);
    kmid<<<NCTA, 256>>>(g1, b1, g2, b2, lw1, lb1, lw2, lb2);
    k4<<<BB * CC * 8, 256>>>(x, out);
}

// round 13
// speedup vs baseline: 1.0641x; 1.0641x over previous
#include <cuda_runtime.h>

#define BB 2
#define CC 512
#define HH 256
#define WW 256
#define EPSV 1e-5f
#define NCTA 148            // persistent-kernel grid for kmid

#define CHUNK_ROWS 16
#define CHUNK_BYTES (CHUNK_ROWS * WW * 4)   // 16 KB
#define NCHUNK (HH / CHUNK_ROWS)            // 16

// ---------------- scratch (device globals; no allocations allowed) ----------
__device__ float g_y1[BB * CC * WW];     // [b][c][w]
__device__ float g_y2[BB * CC * HH];     // [b][c][h]
__device__ float g_dot[CC * BB];         // flat [c][b]; linear view == num[b][k]
__device__ float g_h[BB * 2 * CC];       // [b][1024]
__device__ float g_logits[BB * CC];      // [b][c]
__device__ float g_scale[BB * CC];       // [b][c]

__device__ unsigned g_cnt[3];            // grid-barrier arrival counters
__device__ unsigned g_gen[3];            // grid-barrier generations (monotone)

__device__ __forceinline__ float4 ldcg4(const float4* p) { return __ldcg(p); }
__device__ __forceinline__ void prefetchL2(const void* p) {
    asm volatile("prefetch.global.L2 [%0];" :: "l"(p));
}
__device__ __forceinline__ float hsum4(float4 a) { return (a.x + a.y) + (a.z + a.w); }
__device__ __forceinline__ float dotp4(float4 a, float4 b) {
    return a.x * b.x + a.y * b.y + a.z * b.z + a.w * b.w;
}
__device__ __forceinline__ float4 relu4(float4 a, float r, float c) {
    float4 o;
    o.x = fmaxf(0.f, fmaf(a.x, r, c));
    o.y = fmaxf(0.f, fmaf(a.y, r, c));
    o.z = fmaxf(0.f, fmaf(a.z, r, c));
    o.w = fmaxf(0.f, fmaf(a.w, r, c));
    return o;
}

// ============================================================================
// k1: per-(b,c) plane: y1[w] = sum_h x[h][w]*w1[h], y2[h] = sum_w x[h][w]*w2[w]
// cp.async (LDGSTS) pipeline: fetch is decoupled from compute, so memory-level
// parallelism is no longer bounded by registers/occupancy. 2-stage double
// buffer of 16KB chunks. grid = B*C = 1024, block = 256 (8 warps).
// Per stage: warp w owns rows {2w, 2w+1}; half-warp h covers one row, lane's
// colgroup cg owns float4 columns {cg, cg+16, cg+32, cg+48} (conflict-free LDS).
// ============================================================================
__global__ __launch_bounds__(256) void k1(const float* __restrict__ x,
                                          const float* __restrict__ w1,
                                          const float* __restrict__ w2) {
    __shared__ float4 buf[2][CHUNK_BYTES / 16];   // 2 x 16KB
    __shared__ float4 y1buf[8][64];               // 8KB: per-warp y1 partials
    __shared__ float  w1s[HH];                    // 1KB

    int bc = blockIdx.x;                 // b*CC + c
    int c  = bc & (CC - 1);
    const char* gbase = (const char*)x + (size_t)bc * (HH * WW * 4);

    int t    = threadIdx.x;
    int lane = t & 31;
    int w    = t >> 5;
    int h    = lane >> 4;                // half-warp (row select)
    int cg   = lane & 15;                // colgroup

    w1s[t] = w1[c * HH + t];

    // per-thread w2 quads for float4 columns {cg, cg+16, cg+32, cg+48}
    float4 w2r0 = *(const float4*)(w2 + c * WW + (cg +  0) * 4);
    float4 w2r1 = *(const float4*)(w2 + c * WW + (cg + 16) * 4);
    float4 w2r2 = *(const float4*)(w2 + c * WW + (cg + 32) * 4);
    float4 w2r3 = *(const float4*)(w2 + c * WW + (cg + 48) * 4);

    unsigned sbase0 = (unsigned)__cvta_generic_to_shared(&buf[0][0]);
    unsigned sbase1 = (unsigned)__cvta_generic_to_shared(&buf[1][0]);

    // issue stage s into buf[s&1]: each thread copies 4 x 16B (coalesced)
    auto issue = [&](int s) {
        unsigned sb = (s & 1) ? sbase1 : sbase0;
        const char* g = gbase + (size_t)s * CHUNK_BYTES;
        #pragma unroll
        for (int i = 0; i < 4; ++i) {
            asm volatile("cp.async.cg.shared.global [%0], [%1], 16;"
                         :: "r"(sb + t * 16 + i * 4096), "l"(g + t * 16 + i * 4096)
                         : "memory");
        }
        asm volatile("cp.async.commit_group;" ::: "memory");
    };

    issue(0);
    issue(1);

    float4 acc0 = make_float4(0.f, 0.f, 0.f, 0.f);
    float4 acc1 = make_float4(0.f, 0.f, 0.f, 0.f);
    float4 acc2 = make_float4(0.f, 0.f, 0.f, 0.f);
    float4 acc3 = make_float4(0.f, 0.f, 0.f, 0.f);

    int row = 2 * w + h;                 // row within chunk, 0..15

    #pragma unroll 1
    for (int s = 0; s < NCHUNK; ++s) {
        // groups committed so far: s+2 (stages 0..s+1). wait all but newest 1
        // => stages 0..s complete.
        asm volatile("cp.async.wait_group 1;" ::: "memory");
        __syncthreads();

        const float4* rp = &buf[s & 1][row * 64];
        float4 v0 = rp[cg +  0];
        float4 v1 = rp[cg + 16];
        float4 v2 = rp[cg + 32];
        float4 v3 = rp[cg + 48];

        float wv = w1s[s * CHUNK_ROWS + row];
        acc0.x = fmaf(v0.x, wv, acc0.x); acc0.y = fmaf(v0.y, wv, acc0.y);
        acc0.z = fmaf(v0.z, wv, acc0.z); acc0.w = fmaf(v0.w, wv, acc0.w);
        acc1.x = fmaf(v1.x, wv, acc1.x); acc1.y = fmaf(v1.y, wv, acc1.y);
        acc1.z = fmaf(v1.z, wv, acc1.z); acc1.w = fmaf(v1.w, wv, acc1.w);
        acc2.x = fmaf(v2.x, wv, acc2.x); acc2.y = fmaf(v2.y, wv, acc2.y);
        acc2.z = fmaf(v2.z, wv, acc2.z); acc2.w = fmaf(v2.w, wv, acc2.w);
        acc3.x = fmaf(v3.x, wv, acc3.x); acc3.y = fmaf(v3.y, wv, acc3.y);
        acc3.z = fmaf(v3.z, wv, acc3.z); acc3.w = fmaf(v3.w, wv, acc3.w);

        float p = dotp4(v0, w2r0) + dotp4(v1, w2r1) + dotp4(v2, w2r2) + dotp4(v3, w2r3);
        p += __shfl_xor_sync(0xffffffffu, p, 8);
        p += __shfl_xor_sync(0xffffffffu, p, 4);
        p += __shfl_xor_sync(0xffffffffu, p, 2);
        p += __shfl_xor_sync(0xffffffffu, p, 1);
        if (cg == 0) g_y2[bc * HH + s * CHUNK_ROWS + row] = p;

        __syncthreads();                 // everyone done reading buf[s&1]
        if (s + 2 < NCHUNK) issue(s + 2);
        else asm volatile("cp.async.commit_group;" ::: "memory");  // keep count
    }

    // combine the two half-warps (rows 2w and 2w+1 share columns)
    #pragma unroll
    for (int comp = 0; comp < 1; ++comp) { /* unrolled manually below */ }
    acc0.x += __shfl_down_sync(0xffffffffu, acc0.x, 16);
    acc0.y += __shfl_down_sync(0xffffffffu, acc0.y, 16);
    acc0.z += __shfl_down_sync(0xffffffffu, acc0.z, 16);
    acc0.w += __shfl_down_sync(0xffffffffu, acc0.w, 16);
    acc1.x += __shfl_down_sync(0xffffffffu, acc1.x, 16);
    acc1.y += __shfl_down_sync(0xffffffffu, acc1.y, 16);
    acc1.z += __shfl_down_sync(0xffffffffu, acc1.z, 16);
    acc1.w += __shfl_down_sync(0xffffffffu, acc1.w, 16);
    acc2.x += __shfl_down_sync(0xffffffffu, acc2.x, 16);
    acc2.y += __shfl_down_sync(0xffffffffu, acc2.y, 16);
    acc2.z += __shfl_down_sync(0xffffffffu, acc2.z, 16);
    acc2.w += __shfl_down_sync(0xffffffffu, acc2.w, 16);
    acc3.x += __shfl_down_sync(0xffffffffu, acc3.x, 16);
    acc3.y += __shfl_down_sync(0xffffffffu, acc3.y, 16);
    acc3.z += __shfl_down_sync(0xffffffffu, acc3.z, 16);
    acc3.w += __shfl_down_sync(0xffffffffu, acc3.w, 16);

    if (h == 0) {
        y1buf[w][cg +  0] = acc0;
        y1buf[w][cg + 16] = acc1;
        y1buf[w][cg + 32] = acc2;
        y1buf[w][cg + 48] = acc3;
    }
    __syncthreads();

    if (t < 64) {
        float4 s = y1buf[0][t];
        #pragma unroll
        for (int i = 1; i < 8; ++i) {
            float4 a = y1buf[i][t];
            s.x += a.x; s.y += a.y; s.z += a.z; s.w += a.w;
        }
        reinterpret_cast<float4*>(g_y1 + (size_t)bc * WW)[t] = s;
    }
}

// ============================================================================
// software grid barrier: all NCTA CTAs co-resident (NCTA <= #SMs).
// ============================================================================
__device__ __forceinline__ void gridbar(int i) {
    __syncthreads();
    if (threadIdx.x == 0) {
        __threadfence();
        volatile unsigned* genp = (volatile unsigned*)&g_gen[i];
        unsigned gen = *genp;                          // read BEFORE arriving
        unsigned arrived = atomicAdd(&g_cnt[i], 1u);
        if (arrived == NCTA - 1) {
            atomicExch(&g_cnt[i], 0u);                 // reset for next replay
            __threadfence();
            atomicAdd(&g_gen[i], 1u);                  // release
        } else {
            while (*genp == gen) { __nanosleep(32); }
        }
        __threadfence();
    }
    __syncthreads();
}

// ============================================================================
// kmid: fused BN+ReLU+dot -> linear1 -> linear2 -> softmax.
// Persistent, grid = NCTA, block = 256. MLP weights prefetched into L2.
// ============================================================================
__global__ __launch_bounds__(256) void kmid(const float* __restrict__ g1, const float* __restrict__ b1,
                                            const float* __restrict__ g2, const float* __restrict__ b2,
                                            const float* __restrict__ lw1, const float* __restrict__ lb1,
                                            const float* __restrict__ lw2, const float* __restrict__ lb2) {
    int t    = threadIdx.x;
    int lane = t & 31;
    int wrp  = t >> 5;
    int gw   = blockIdx.x * 8 + wrp;

    // ---- prefetch MLP weights into L2 (1 line per thread) ----
    {
        int gt = blockIdx.x * 256 + t;
        if (gt < 16384)          prefetchL2((const char*)lw1 + (size_t)gt * 128);
        else if (gt < 32768)     prefetchL2((const char*)lw2 + (size_t)(gt - 16384) * 128);
    }

    // ---- phase A: per-channel BN stats + ReLU + dot (one warp per channel) --
    if (gw < CC) {
        int c = gw;
        const float4* p10 = reinterpret_cast<const float4*>(g_y1 + c * WW);
        const float4* p11 = reinterpret_cast<const float4*>(g_y1 + CC * WW + c * WW);
        const float4* p20 = reinterpret_cast<const float4*>(g_y2 + c * HH);
        const float4* p21 = reinterpret_cast<const float4*>(g_y2 + CC * HH + c * HH);

        float4 a10a = ldcg4(p10 + lane), a10b = ldcg4(p10 + lane + 32);
        float4 a11a = ldcg4(p11 + lane), a11b = ldcg4(p11 + lane + 32);
        float4 a20a = ldcg4(p20 + lane), a20b = ldcg4(p20 + lane + 32);
        float4 a21a = ldcg4(p21 + lane), a21b = ldcg4(p21 + lane + 32);

        float s1 = hsum4(a10a) + hsum4(a10b) + hsum4(a11a) + hsum4(a11b);
        float q1 = dotp4(a10a, a10a) + dotp4(a10b, a10b) + dotp4(a11a, a11a) + dotp4(a11b, a11b);
        float s2 = hsum4(a20a) + hsum4(a20b) + hsum4(a21a) + hsum4(a21b);
        float q2 = dotp4(a20a, a20a) + dotp4(a20b, a20b) + dotp4(a21a, a21a) + dotp4(a21b, a21b);

        #pragma unroll
        for (int off = 16; off; off >>= 1) {
            s1 += __shfl_xor_sync(0xffffffffu, s1, off);
            q1 += __shfl_xor_sync(0xffffffffu, q1, off);
            s2 += __shfl_xor_sync(0xffffffffu, s2, off);
            q2 += __shfl_xor_sync(0xffffffffu, q2, off);
        }

        const float invn = 1.f / (float)(BB * WW);
        float m1 = s1 * invn, v1 = q1 * invn - m1 * m1;
        float m2 = s2 * invn, v2 = q2 * invn - m2 * m2;
        float r1 = rsqrtf(v1 + EPSV) * g1[c];
        float c1 = b1[c] - m1 * r1;
        float r2 = rsqrtf(v2 + EPSV) * g2[c];
        float c2 = b2[c] - m2 * r2;

        float d0 = dotp4(relu4(a10a, r1, c1), relu4(a20a, r2, c2))
                 + dotp4(relu4(a10b, r1, c1), relu4(a20b, r2, c2));
        float d1 = dotp4(relu4(a11a, r1, c1), relu4(a21a, r2, c2))
                 + dotp4(relu4(a11b, r1, c1), relu4(a21b, r2, c2));
        #pragma unroll
        for (int off = 16; off; off >>= 1) {
            d0 += __shfl_xor_sync(0xffffffffu, d0, off);
            d1 += __shfl_xor_sync(0xffffffffu, d1, off);
        }
        if (lane == 0) {
            g_dot[c * BB + 0] = d0;
            g_dot[c * BB + 1] = d1;
        }
    }

    gridbar(0);

    // ---- phase B: layer1, one warp per output row j (K=512) ----
    if (gw < 2 * CC) {
        int j = gw;
        const float4* wr = reinterpret_cast<const float4*>(lw1 + (size_t)j * CC);
        const float4* i0 = reinterpret_cast<const float4*>(g_dot);
        const float4* i1 = reinterpret_cast<const float4*>(g_dot + CC);
        float a0 = 0.f, a1 = 0.f;
        #pragma unroll
        for (int i = 0; i < 4; ++i) {
            float4 wq = __ldg(wr + lane + 32 * i);
            float4 v0 = ldcg4(i0 + lane + 32 * i);
            float4 v1 = ldcg4(i1 + lane + 32 * i);
            a0 += dotp4(wq, v0);
            a1 += dotp4(wq, v1);
        }
        #pragma unroll
        for (int off = 16; off; off >>= 1) {
            a0 += __shfl_xor_sync(0xffffffffu, a0, off);
            a1 += __shfl_xor_sync(0xffffffffu, a1, off);
        }
        if (lane == 0) {
            float bj = lb1[j];
            g_h[j]          = a0 + bj;
            g_h[2 * CC + j] = a1 + bj;
        }
    }

    gridbar(1);

    // ---- phase C: layer2, one warp per output row j (K=1024) ----
    if (gw < CC) {
        int j = gw;
        const float4* wr = reinterpret_cast<const float4*>(lw2 + (size_t)j * 2 * CC);
        const float4* i0 = reinterpret_cast<const float4*>(g_h);
        const float4* i1 = reinterpret_cast<const float4*>(g_h + 2 * CC);
        float a0 = 0.f, a1 = 0.f;
        #pragma unroll
        for (int i = 0; i < 8; ++i) {
            float4 wq = __ldg(wr + lane + 32 * i);
            float4 v0 = ldcg4(i0 + lane + 32 * i);
            float4 v1 = ldcg4(i1 + lane + 32 * i);
            a0 += dotp4(wq, v0);
            a1 += dotp4(wq, v1);
        }
        #pragma unroll
        for (int off = 16; off; off >>= 1) {
            a0 += __shfl_xor_sync(0xffffffffu, a0, off);
            a1 += __shfl_xor_sync(0xffffffffu, a1, off);
        }
        if (lane == 0) {
            float bj = lb2[j];
            g_logits[j]      = a0 + bj;
            g_logits[CC + j] = a1 + bj;
        }
    }

    gridbar(2);

    // ---- phase D: softmax over c per batch; CTA 0 only ----
    if (blockIdx.x == 0) {
        __shared__ float sh[8];
        #pragma unroll
        for (int b = 0; b < BB; ++b) {
            float v0 = __ldcg(&g_logits[b * CC + t]);
            float v1 = __ldcg(&g_logits[b * CC + 256 + t]);

            float m = fmaxf(v0, v1);
            #pragma unroll
            for (int off = 16; off; off >>= 1) m = fmaxf(m, __shfl_xor_sync(0xffffffffu, m, off));
            if (lane == 0) sh[wrp] = m;
            __syncthreads();
            if (t == 0) {
                float mm = sh[0];
                #pragma unroll
                for (int i = 1; i < 8; ++i) mm = fmaxf(mm, sh[i]);
                sh[0] = mm;
            }
            __syncthreads();
            m = sh[0];
            __syncthreads();

            float e0 = expf(v0 - m), e1 = expf(v1 - m);
            float s = e0 + e1;
            #pragma unroll
            for (int off = 16; off; off >>= 1) s += __shfl_xor_sync(0xffffffffu, s, off);
            if (lane == 0) sh[wrp] = s;
            __syncthreads();
            if (t == 0) {
                float ss = sh[0];
                #pragma unroll
                for (int i = 1; i < 8; ++i) ss += sh[i];
                sh[0] = ss;
            }
            __syncthreads();
            s = sh[0];
            __syncthreads();

            float inv = 1.f / s;
            g_scale[b * CC + t]       = e0 * inv;
            g_scale[b * CC + 256 + t] = e1 * inv;
        }
    }
}

// ============================================================================
// k4: out = x * scale[b,c]. Reversed plane order + streaming stores (the exact
// configuration of the 143.8us best).
// ============================================================================
__global__ __launch_bounds__(256) void k4(const float* __restrict__ x, float* __restrict__ out) {
    int idx  = (BB * CC * 8 - 1) - blockIdx.x;   // reversed schedule
    int bc   = idx >> 3;
    int part = idx & 7;
    float s = __ldcg(&g_scale[bc]);

    const float4* xp = reinterpret_cast<const float4*>(x)   + (size_t)bc * (HH * WW / 4) + part * 2048;
    float4*       op = reinterpret_cast<float4*>(out)       + (size_t)bc * (HH * WW / 4) + part * 2048;

    int t = threadIdx.x;
    #pragma unroll
    for (int i = 0; i < 8; ++i) {
        float4 v = xp[i * 256 + t];
        v.x *= s; v.y *= s; v.z *= s; v.w *= s;
        __stcs(&op[i * 256 + t], v);
    }
}

// ============================================================================
extern "C" void kernel_launch(void* const* d_in, const int* in_sizes, int n_in,
                              void* d_out, int out_size) {
    const float* x   = (const float*)d_in[0];
    const float* w1  = (const float*)d_in[1];
    const float* w2  = (const float*)d_in[2];
    const float* g1  = (const float*)d_in[3];
    const float* b1  = (const float*)d_in[4];
    const float* g2  = (const float*)d_in[5];
    const float* b2  = (const float*)d_in[6];
    const float* lw1 = (const float*)d_in[7];
    const float* lb1 = (const float*)d_in[8];
    const float* lw2 = (const float*)d_in[9];
    const float* lb2 = (const float*)d_in[10];
    float* out = (float*)d_out;

    k1<<<BB * CC, 256>>>(x, w1, w2);
    kmid<<<NCTA, 256>>>(g1, b1, g2, b2, lw1, lb1, lw2, lb2);
    k4<<<BB * CC * 8, 256>>>(x, out);
}

// round 15
// speedup vs baseline: 1.0797x; 1.0147x over previous
#include <cuda_runtime.h>

#define BB 2
#define CC 512
#define HH 256
#define WW 256
#define EPSV 1e-5f
#define NCTA 148            // persistent-kernel grid for kmid

#define CHUNK_ROWS 16
#define CHUNK_BYTES (CHUNK_ROWS * WW * 4)   // 16 KB
#define QROWS 64                            // rows per work unit (quarter plane)
#define NCHUNK (QROWS / CHUNK_ROWS)         // 4 chunks per unit
#define NUNIT (BB * CC * 4)                 // 4096 work units

// ---------------- scratch (device globals; no allocations allowed) ----------
__device__ float g_y1p[4 * BB * CC * WW];   // [q][b*CC+c][w]  y1 partials (4 MB)
__device__ float g_y2[BB * CC * HH];        // [b][c][h]
__device__ float g_dot[CC * BB];            // flat [c][b]; linear view == num[b][k]
__device__ float g_h[BB * 2 * CC];          // [b][1024]
__device__ float g_logits[BB * CC];         // [b][c]
__device__ float g_scale[BB * CC];          // [b][c]

__device__ unsigned g_cnt[3];               // grid-barrier arrival counters
__device__ unsigned g_gen[3];               // grid-barrier generations (monotone)

__device__ __forceinline__ float4 ldcg4(const float4* p) { return __ldcg(p); }
__device__ __forceinline__ void prefetchL2(const void* p) {
    asm volatile("prefetch.global.L2 [%0];" :: "l"(p));
}
__device__ __forceinline__ float hsum4(float4 a) { return (a.x + a.y) + (a.z + a.w); }
__device__ __forceinline__ float dotp4(float4 a, float4 b) {
    return a.x * b.x + a.y * b.y + a.z * b.z + a.w * b.w;
}
__device__ __forceinline__ float4 relu4(float4 a, float r, float c) {
    float4 o;
    o.x = fmaxf(0.f, fmaf(a.x, r, c));
    o.y = fmaxf(0.f, fmaf(a.y, r, c));
    o.z = fmaxf(0.f, fmaf(a.z, r, c));
    o.w = fmaxf(0.f, fmaf(a.w, r, c));
    return o;
}
__device__ __forceinline__ void add4(float4& s, float4 a) {
    s.x += a.x; s.y += a.y; s.z += a.z; s.w += a.w;
}

// ============================================================================
// k1: quarter-plane work units to kill wave quantization (4096 units over
// ~592 concurrent CTA slots => 7 waves, 98.8% fill, vs 1.73 waves / 86.5%).
// Each unit: rows [qt*64, qt*64+64) of plane bc. cp.async double-buffered
// pipeline of 16KB chunks. y1 column sums are per-quarter partials into
// g_y1p[qt]; y2 rows are disjoint per unit and written directly.
// Per stage: warp w owns rows {2w, 2w+1}; half-warp h covers one row; lane's
// colgroup cg owns float4 columns {cg, cg+16, cg+32, cg+48} (conflict-free).
// ============================================================================
__global__ __launch_bounds__(256) void k1(const float* __restrict__ x,
                                          const float* __restrict__ w1,
                                          const float* __restrict__ w2) {
    __shared__ float4 buf[2][CHUNK_BYTES / 16];   // 2 x 16KB
    __shared__ float4 y1buf[8][64];               // 8KB: per-warp y1 partials
    __shared__ float  w1s[QROWS];                 // 256B

    int unit = blockIdx.x;               // 0..4095
    int bc   = unit >> 2;                // plane index b*CC + c
    int qt   = unit & 3;                 // quarter index
    int c    = bc & (CC - 1);
    const char* gbase = (const char*)x + (size_t)bc * (HH * WW * 4) + (size_t)qt * (QROWS * WW * 4);

    int t    = threadIdx.x;
    int lane = t & 31;
    int w    = t >> 5;
    int h    = lane >> 4;                // half-warp (row select)
    int cg   = lane & 15;                // colgroup

    if (t < QROWS) w1s[t] = w1[c * HH + qt * QROWS + t];

    // per-thread w2 quads for float4 columns {cg, cg+16, cg+32, cg+48}
    float4 w2r0 = *(const float4*)(w2 + c * WW + (cg +  0) * 4);
    float4 w2r1 = *(const float4*)(w2 + c * WW + (cg + 16) * 4);
    float4 w2r2 = *(const float4*)(w2 + c * WW + (cg + 32) * 4);
    float4 w2r3 = *(const float4*)(w2 + c * WW + (cg + 48) * 4);

    unsigned sbase0 = (unsigned)__cvta_generic_to_shared(&buf[0][0]);
    unsigned sbase1 = (unsigned)__cvta_generic_to_shared(&buf[1][0]);

    // issue stage s into buf[s&1]: each thread copies 4 x 16B (coalesced)
    auto issue = [&](int s) {
        unsigned sb = (s & 1) ? sbase1 : sbase0;
        const char* g = gbase + (size_t)s * CHUNK_BYTES;
        #pragma unroll
        for (int i = 0; i < 4; ++i) {
            asm volatile("cp.async.cg.shared.global [%0], [%1], 16;"
                         :: "r"(sb + t * 16 + i * 4096), "l"(g + t * 16 + i * 4096)
                         : "memory");
        }
        asm volatile("cp.async.commit_group;" ::: "memory");
    };

    issue(0);
    issue(1);

    float4 acc0 = make_float4(0.f, 0.f, 0.f, 0.f);
    float4 acc1 = make_float4(0.f, 0.f, 0.f, 0.f);
    float4 acc2 = make_float4(0.f, 0.f, 0.f, 0.f);
    float4 acc3 = make_float4(0.f, 0.f, 0.f, 0.f);

    int row = 2 * w + h;                 // row within chunk, 0..15

    #pragma unroll 1
    for (int s = 0; s < NCHUNK; ++s) {
        // groups committed so far: s+2 (stages 0..s+1). wait all but newest 1
        // => stages 0..s complete.
        asm volatile("cp.async.wait_group 1;" ::: "memory");
        __syncthreads();

        const float4* rp = &buf[s & 1][row * 64];
        float4 v0 = rp[cg +  0];
        float4 v1 = rp[cg + 16];
        float4 v2 = rp[cg + 32];
        float4 v3 = rp[cg + 48];

        float wv = w1s[s * CHUNK_ROWS + row];
        acc0.x = fmaf(v0.x, wv, acc0.x); acc0.y = fmaf(v0.y, wv, acc0.y);
        acc0.z = fmaf(v0.z, wv, acc0.z); acc0.w = fmaf(v0.w, wv, acc0.w);
        acc1.x = fmaf(v1.x, wv, acc1.x); acc1.y = fmaf(v1.y, wv, acc1.y);
        acc1.z = fmaf(v1.z, wv, acc1.z); acc1.w = fmaf(v1.w, wv, acc1.w);
        acc2.x = fmaf(v2.x, wv, acc2.x); acc2.y = fmaf(v2.y, wv, acc2.y);
        acc2.z = fmaf(v2.z, wv, acc2.z); acc2.w = fmaf(v2.w, wv, acc2.w);
        acc3.x = fmaf(v3.x, wv, acc3.x); acc3.y = fmaf(v3.y, wv, acc3.y);
        acc3.z = fmaf(v3.z, wv, acc3.z); acc3.w = fmaf(v3.w, wv, acc3.w);

        float p = dotp4(v0, w2r0) + dotp4(v1, w2r1) + dotp4(v2, w2r2) + dotp4(v3, w2r3);
        p += __shfl_xor_sync(0xffffffffu, p, 8);
        p += __shfl_xor_sync(0xffffffffu, p, 4);
        p += __shfl_xor_sync(0xffffffffu, p, 2);
        p += __shfl_xor_sync(0xffffffffu, p, 1);
        if (cg == 0) g_y2[bc * HH + qt * QROWS + s * CHUNK_ROWS + row] = p;

        __syncthreads();                 // everyone done reading buf[s&1]
        if (s + 2 < NCHUNK) issue(s + 2);
        else asm volatile("cp.async.commit_group;" ::: "memory");  // keep count
    }

    // combine the two half-warps (rows 2w and 2w+1 share columns)
    acc0.x += __shfl_down_sync(0xffffffffu, acc0.x, 16);
    acc0.y += __shfl_down_sync(0xffffffffu, acc0.y, 16);
    acc0.z += __shfl_down_sync(0xffffffffu, acc0.z, 16);
    acc0.w += __shfl_down_sync(0xffffffffu, acc0.w, 16);
    acc1.x += __shfl_down_sync(0xffffffffu, acc1.x, 16);
    acc1.y += __shfl_down_sync(0xffffffffu, acc1.y, 16);
    acc1.z += __shfl_down_sync(0xffffffffu, acc1.z, 16);
    acc1.w += __shfl_down_sync(0xffffffffu, acc1.w, 16);
    acc2.x += __shfl_down_sync(0xffffffffu, acc2.x, 16);
    acc2.y += __shfl_down_sync(0xffffffffu, acc2.y, 16);
    acc2.z += __shfl_down_sync(0xffffffffu, acc2.z, 16);
    acc2.w += __shfl_down_sync(0xffffffffu, acc2.w, 16);
    acc3.x += __shfl_down_sync(0xffffffffu, acc3.x, 16);
    acc3.y += __shfl_down_sync(0xffffffffu, acc3.y, 16);
    acc3.z += __shfl_down_sync(0xffffffffu, acc3.z, 16);
    acc3.w += __shfl_down_sync(0xffffffffu, acc3.w, 16);

    if (h == 0) {
        y1buf[w][cg +  0] = acc0;
        y1buf[w][cg + 16] = acc1;
        y1buf[w][cg + 32] = acc2;
        y1buf[w][cg + 48] = acc3;
    }
    __syncthreads();

    if (t < 64) {
        float4 s = y1buf[0][t];
        #pragma unroll
        for (int i = 1; i < 8; ++i) add4(s, y1buf[i][t]);
        reinterpret_cast<float4*>(g_y1p + ((size_t)qt * BB * CC + bc) * WW)[t] = s;
    }
}

// ============================================================================
// software grid barrier: all NCTA CTAs co-resident (NCTA <= #SMs).
// ============================================================================
__device__ __forceinline__ void gridbar(int i) {
    __syncthreads();
    if (threadIdx.x == 0) {
        __threadfence();
        volatile unsigned* genp = (volatile unsigned*)&g_gen[i];
        unsigned gen = *genp;                          // read BEFORE arriving
        unsigned arrived = atomicAdd(&g_cnt[i], 1u);
        if (arrived == NCTA - 1) {
            atomicExch(&g_cnt[i], 0u);                 // reset for next replay
            __threadfence();
            atomicAdd(&g_gen[i], 1u);                  // release
        } else {
            while (*genp == gen) { __nanosleep(32); }
        }
        __threadfence();
    }
    __syncthreads();
}

// ============================================================================
// kmid: fused BN+ReLU+dot -> linear1 -> linear2 -> softmax.
// Persistent, grid = NCTA, block = 256. MLP weights prefetched into L2.
// Phase A now sums the 4 quarter-partials of y1 (fixed order => deterministic).
// ============================================================================
__global__ __launch_bounds__(256) void kmid(const float* __restrict__ g1, const float* __restrict__ b1,
                                            const float* __restrict__ g2, const float* __restrict__ b2,
                                            const float* __restrict__ lw1, const float* __restrict__ lb1,
                                            const float* __restrict__ lw2, const float* __restrict__ lb2) {
    int t    = threadIdx.x;
    int lane = t & 31;
    int wrp  = t >> 5;
    int gw   = blockIdx.x * 8 + wrp;

    // ---- prefetch MLP weights into L2 (1 line per thread) ----
    {
        int gt = blockIdx.x * 256 + t;
        if (gt < 16384)          prefetchL2((const char*)lw1 + (size_t)gt * 128);
        else if (gt < 32768)     prefetchL2((const char*)lw2 + (size_t)(gt - 16384) * 128);
    }

    // ---- phase A: per-channel BN stats + ReLU + dot (one warp per channel) --
    if (gw < CC) {
        int c = gw;
        const size_t QS = (size_t)BB * CC * WW / 4;   // quarter stride (float4)
        const float4* y1b = reinterpret_cast<const float4*>(g_y1p);
        const float4* p20 = reinterpret_cast<const float4*>(g_y2 + c * HH);
        const float4* p21 = reinterpret_cast<const float4*>(g_y2 + CC * HH + c * HH);

        float4 a10a = make_float4(0.f, 0.f, 0.f, 0.f);
        float4 a10b = make_float4(0.f, 0.f, 0.f, 0.f);
        float4 a11a = make_float4(0.f, 0.f, 0.f, 0.f);
        float4 a11b = make_float4(0.f, 0.f, 0.f, 0.f);
        #pragma unroll
        for (int q = 0; q < 4; ++q) {
            add4(a10a, ldcg4(y1b + q * QS + (size_t)c * 64 + lane));
            add4(a10b, ldcg4(y1b + q * QS + (size_t)c * 64 + lane + 32));
            add4(a11a, ldcg4(y1b + q * QS + (size_t)(CC + c) * 64 + lane));
            add4(a11b, ldcg4(y1b + q * QS + (size_t)(CC + c) * 64 + lane + 32));
        }

        float4 a20a = ldcg4(p20 + lane), a20b = ldcg4(p20 + lane + 32);
        float4 a21a = ldcg4(p21 + lane), a21b = ldcg4(p21 + lane + 32);

        float s1 = hsum4(a10a) + hsum4(a10b) + hsum4(a11a) + hsum4(a11b);
        float q1 = dotp4(a10a, a10a) + dotp4(a10b, a10b) + dotp4(a11a, a11a) + dotp4(a11b, a11b);
        float s2 = hsum4(a20a) + hsum4(a20b) + hsum4(a21a) + hsum4(a21b);
        float q2 = dotp4(a20a, a20a) + dotp4(a20b, a20b) + dotp4(a21a, a21a) + dotp4(a21b, a21b);

        #pragma unroll
        for (int off = 16; off; off >>= 1) {
            s1 += __shfl_xor_sync(0xffffffffu, s1, off);
            q1 += __shfl_xor_sync(0xffffffffu, q1, off);
            s2 += __shfl_xor_sync(0xffffffffu, s2, off);
            q2 += __shfl_xor_sync(0xffffffffu, q2, off);
        }

        const float invn = 1.f / (float)(BB * WW);
        float m1 = s1 * invn, v1 = q1 * invn - m1 * m1;
        float m2 = s2 * invn, v2 = q2 * invn - m2 * m2;
        float r1 = rsqrtf(v1 + EPSV) * g1[c];
        float c1 = b1[c] - m1 * r1;
        float r2 = rsqrtf(v2 + EPSV) * g2[c];
        float c2 = b2[c] - m2 * r2;

        float d0 = dotp4(relu4(a10a, r1, c1), relu4(a20a, r2, c2))
                 + dotp4(relu4(a10b, r1, c1), relu4(a20b, r2, c2));
        float d1 = dotp4(relu4(a11a, r1, c1), relu4(a21a, r2, c2))
                 + dotp4(relu4(a11b, r1, c1), relu4(a21b, r2, c2));
        #pragma unroll
        for (int off = 16; off; off >>= 1) {
            d0 += __shfl_xor_sync(0xffffffffu, d0, off);
            d1 += __shfl_xor_sync(0xffffffffu, d1, off);
        }
        if (lane == 0) {
            g_dot[c * BB + 0] = d0;
            g_dot[c * BB + 1] = d1;
        }
    }

    gridbar(0);

    // ---- phase B: layer1, one warp per output row j (K=512) ----
    if (gw < 2 * CC) {
        int j = gw;
        const float4* wr = reinterpret_cast<const float4*>(lw1 + (size_t)j * CC);
        const float4* i0 = reinterpret_cast<const float4*>(g_dot);
        const float4* i1 = reinterpret_cast<const float4*>(g_dot + CC);
        float a0 = 0.f, a1 = 0.f;
        #pragma unroll
        for (int i = 0; i < 4; ++i) {
            float4 wq = __ldg(wr + lane + 32 * i);
            float4 v0 = ldcg4(i0 + lane + 32 * i);
            float4 v1 = ldcg4(i1 + lane + 32 * i);
            a0 += dotp4(wq, v0);
            a1 += dotp4(wq, v1);
        }
        #pragma unroll
        for (int off = 16; off; off >>= 1) {
            a0 += __shfl_xor_sync(0xffffffffu, a0, off);
            a1 += __shfl_xor_sync(0xffffffffu, a1, off);
        }
        if (lane == 0) {
            float bj = lb1[j];
            g_h[j]          = a0 + bj;
            g_h[2 * CC + j] = a1 + bj;
        }
    }

    gridbar(1);

    // ---- phase C: layer2, one warp per output row j (K=1024) ----
    if (gw < CC) {
        int j = gw;
        const float4* wr = reinterpret_cast<const float4*>(lw2 + (size_t)j * 2 * CC);
        const float4* i0 = reinterpret_cast<const float4*>(g_h);
        const float4* i1 = reinterpret_cast<const float4*>(g_h + 2 * CC);
        float a0 = 0.f, a1 = 0.f;
        #pragma unroll
        for (int i = 0; i < 8; ++i) {
            float4 wq = __ldg(wr + lane + 32 * i);
            float4 v0 = ldcg4(i0 + lane + 32 * i);
            float4 v1 = ldcg4(i1 + lane + 32 * i);
            a0 += dotp4(wq, v0);
            a1 += dotp4(wq, v1);
        }
        #pragma unroll
        for (int off = 16; off; off >>= 1) {
            a0 += __shfl_xor_sync(0xffffffffu, a0, off);
            a1 += __shfl_xor_sync(0xffffffffu, a1, off);
        }
        if (lane == 0) {
            float bj = lb2[j];
            g_logits[j]      = a0 + bj;
            g_logits[CC + j] = a1 + bj;
        }
    }

    gridbar(2);

    // ---- phase D: softmax over c per batch; CTA 0 only ----
    if (blockIdx.x == 0) {
        __shared__ float sh[8];
        #pragma unroll
        for (int b = 0; b < BB; ++b) {
            float v0 = __ldcg(&g_logits[b * CC + t]);
            float v1 = __ldcg(&g_logits[b * CC + 256 + t]);

            float m = fmaxf(v0, v1);
            #pragma unroll
            for (int off = 16; off; off >>= 1) m = fmaxf(m, __shfl_xor_sync(0xffffffffu, m, off));
            if (lane == 0) sh[wrp] = m;
            __syncthreads();
            if (t == 0) {
                float mm = sh[0];
                #pragma unroll
                for (int i = 1; i < 8; ++i) mm = fmaxf(mm, sh[i]);
                sh[0] = mm;
            }
            __syncthreads();
            m = sh[0];
            __syncthreads();

            float e0 = expf(v0 - m), e1 = expf(v1 - m);
            float s = e0 + e1;
            #pragma unroll
            for (int off = 16; off; off >>= 1) s += __shfl_xor_sync(0xffffffffu, s, off);
            if (lane == 0) sh[wrp] = s;
            __syncthreads();
            if (t == 0) {
                float ss = sh[0];
                #pragma unroll
                for (int i = 1; i < 8; ++i) ss += sh[i];
                sh[0] = ss;
            }
            __syncthreads();
            s = sh[0];
            __syncthreads();

            float inv = 1.f / s;
            g_scale[b * CC + t]       = e0 * inv;
            g_scale[b * CC + 256 + t] = e1 * inv;
        }
    }
}

// ============================================================================
// k4: out = x * scale[b,c]. Reversed plane order + streaming stores (the exact
// configuration of the best run).
// ============================================================================
__global__ __launch_bounds__(256) void k4(const float* __restrict__ x, float* __restrict__ out) {
    int idx  = (BB * CC * 8 - 1) - blockIdx.x;   // reversed schedule
    int bc   = idx >> 3;
    int part = idx & 7;
    float s = __ldcg(&g_scale[bc]);

    const float4* xp = reinterpret_cast<const float4*>(x)   + (size_t)bc * (HH * WW / 4) + part * 2048;
    float4*       op = reinterpret_cast<float4*>(out)       + (size_t)bc * (HH * WW / 4) + part * 2048;

    int t = threadIdx.x;
    #pragma unroll
    for (int i = 0; i < 8; ++i) {
        float4 v = xp[i * 256 + t];
        v.x *= s; v.y *= s; v.z *= s; v.w *= s;
        __stcs(&op[i * 256 + t], v);
    }
}

// ============================================================================
extern "C" void kernel_launch(void* const* d_in, const int* in_sizes, int n_in,
                              void* d_out, int out_size) {
    const float* x   = (const float*)d_in[0];
    const float* w1  = (const float*)d_in[1];
    const float* w2  = (const float*)d_in[2];
    const float* g1  = (const float*)d_in[3];
    const float* b1  = (const float*)d_in[4];
    const float* g2  = (const float*)d_in[5];
    const float* b2  = (const float*)d_in[6];
    const float* lw1 = (const float*)d_in[7];
    const float* lb1 = (const float*)d_in[8];
    const float* lw2 = (const float*)d_in[9];
    const float* lb2 = (const float*)d_in[10];
    float* out = (float*)d_out;

    k1<<<NUNIT, 256>>>(x, w1, w2);
    kmid<<<NCTA, 256>>>(g1, b1, g2, b2, lw1, lb1, lw2, lb2);
    k4<<<BB * CC * 8, 256>>>(x, out);
}